// round 6
// baseline (speedup 1.0000x reference)
#include <cuda_runtime.h>

// out[p, :] = cumsum(W, axis=1)[:, x[p]] + b, p in [0, 8192*200)
// x: int32 (NPOS), W: fp32 (64,129) row-major, b: fp32 (64), out: fp32 (NPOS*64)

#define F1 129                  // num_feature + 1
#define D  64                   // vector dim
#define NPOS (8192 * 200)       // 1,638,400 positions (divisible by 32)
#define TPB 256
#define WARPS_PB (TPB / 32)

__global__ void __launch_bounds__(TPB, 6)
embed_kernel(const int* __restrict__ x,
             const float* __restrict__ W,
             const float* __restrict__ b,
             float* __restrict__ out) {
    // tab[c*64 + d] = b[d] + sum_{j<=c} W[d*F1 + j]; 33,024 B
    __shared__ float tab[F1 * D];
    __shared__ float seg_carry[4][D];      // per-dim segment sums

    // ---- parallel table build: 256 threads = 4 segments x 64 dims ----
    const int t   = threadIdx.x;
    const int d   = t & 63;
    const int seg = t >> 6;                // 0..3
    const int start = seg * 33;            // 0,33,66,99
    const int cnt   = (seg == 3) ? 30 : 33;

    // Pass 1: stage raw W into tab (scratch) + compute segment sum.
    {
        const float* wrow = W + d * F1 + start;
        float s = 0.f;
        int j = 0;
        for (; j + 8 <= cnt; j += 8) {
            float v[8];
            #pragma unroll
            for (int u = 0; u < 8; ++u) v[u] = __ldg(&wrow[j + u]);
            #pragma unroll
            for (int u = 0; u < 8; ++u) {
                s += v[u];
                tab[(start + j + u) * D + d] = v[u];   // raw stage
            }
        }
        for (; j < cnt; ++j) {
            float v = __ldg(&wrow[j]);
            s += v;
            tab[(start + j) * D + d] = v;
        }
        seg_carry[seg][d] = s;
    }
    __syncthreads();

    // Pass 2+3: carry-in for this segment, then in-smem prefix chain.
    {
        float s = __ldg(&b[d]);
        for (int q = 0; q < seg; ++q) s += seg_carry[q][d];
        for (int j = 0; j < cnt; ++j) {
            s += tab[(start + j) * D + d];
            tab[(start + j) * D + d] = s;
        }
    }
    __syncthreads();

    const float4* tab4 = reinterpret_cast<const float4*>(tab);

    // ---- main gather/store loop ----
    const int lane   = threadIdx.x & 31;
    const int lane15 = lane & 15;          // which float4 within the 64-float row
    const int half   = lane >> 4;          // 0/1: which of each pair of positions
    const int warp   = threadIdx.x >> 5;

    const int gwarp  = blockIdx.x * WARPS_PB + warp;
    const int nwarps = gridDim.x * WARPS_PB;
    const int stride = nwarps * 32;
    float4* __restrict__ o4 = reinterpret_cast<float4*>(out);

    int base = gwarp * 32;
    if (base >= NPOS) return;

    int xv = x[base + lane];                       // coalesced 128B load
    #pragma unroll 1
    for (; base < NPOS; base += stride) {
        const int nbase = base + stride;
        int xv_next = 0;
        if (nbase < NPOS) xv_next = x[nbase + lane];   // prefetch

        // warp covers 32 consecutive positions; store addrs = wbase + k*512B
        float4* wbase = o4 + ((size_t)base + half) * (D / 4) + lane15;
        #pragma unroll
        for (int k = 0; k < 16; ++k) {
            const int xi = __shfl_sync(0xffffffffu, xv, 2 * k + half);
            const float4 v = tab4[xi * (D / 4) + lane15];
            wbase[k * 2 * (D / 4)] = v;        // default write-back store
        }
        xv = xv_next;
    }
}

extern "C" void kernel_launch(void* const* d_in, const int* in_sizes, int n_in,
                              void* d_out, int out_size) {
    const int*   x = (const int*)  d_in[0];
    const float* W = (const float*)d_in[1];
    const float* b = (const float*)d_in[2];
    float*     out = (float*)d_out;

    // Persistent grid: 152 SMs * 6 CTAs (smem-limited ~34KB/CTA)
    const int grid = 152 * 6;
    embed_kernel<<<grid, TPB>>>(x, W, b, out);
}

// round 7
// speedup vs baseline: 1.0756x; 1.0756x over previous
#include <cuda_runtime.h>

// out[p, :] = cumsum(W, axis=1)[:, x[p]] + b, p in [0, 8192*200)
// x: int32 (NPOS), W: fp32 (64,129) row-major, b: fp32 (64), out: fp32 (NPOS*64)

#define F1 129                  // num_feature + 1
#define D  64                   // vector dim
#define NPOS (8192 * 200)       // 1,638,400 positions (divisible by 32)
#define TPB 256
#define WARPS_PB (TPB / 32)

// Lookup table in global memory (L1-resident during gather):
// g_table[c*D + d] = b[d] + sum_{j<=c} W[d*F1 + j]
__device__ float g_table[F1 * D];

// ---- tiny parallel build: 1 block, 256 threads = 4 segments x 64 dims ----
__global__ void build_kernel(const float* __restrict__ W,
                             const float* __restrict__ b) {
    __shared__ float tab[F1 * D];
    __shared__ float carry[4][D];

    const int t   = threadIdx.x;
    const int d   = t & 63;
    const int seg = t >> 6;                 // 0..3
    const int start = seg * 33;             // 0,33,66,99
    const int cnt   = (seg == 3) ? 30 : 33;

    // Pass 1: stage raw W + per-segment sum (batched loads -> short chain)
    {
        const float* wrow = W + d * F1 + start;
        float s = 0.f;
        int j = 0;
        for (; j + 8 <= cnt; j += 8) {
            float v[8];
            #pragma unroll
            for (int u = 0; u < 8; ++u) v[u] = __ldg(&wrow[j + u]);
            #pragma unroll
            for (int u = 0; u < 8; ++u) {
                s += v[u];
                tab[(start + j + u) * D + d] = v[u];
            }
        }
        for (; j < cnt; ++j) {
            float v = __ldg(&wrow[j]);
            s += v;
            tab[(start + j) * D + d] = v;
        }
        carry[seg][d] = s;
    }
    __syncthreads();

    // Pass 2: carry-in, then in-smem prefix chain over this segment
    {
        float s = __ldg(&b[d]);
        for (int q = 0; q < seg; ++q) s += carry[q][d];
        for (int j = 0; j < cnt; ++j) {
            s += tab[(start + j) * D + d];
            tab[(start + j) * D + d] = s;
        }
    }
    __syncthreads();

    // Pass 3: coalesced copy to global table
    for (int i = t; i < F1 * D; i += TPB)
        g_table[i] = tab[i];
}

// ---- gather/store: zero smem -> 8 CTAs/SM (64 warps), table via L1 ----
__global__ void __launch_bounds__(TPB, 8)
gather_kernel(const int* __restrict__ x, float* __restrict__ out) {
    const float4* __restrict__ gt4 = reinterpret_cast<const float4*>(g_table);

    const int lane   = threadIdx.x & 31;
    const int lane15 = lane & 15;          // which float4 within the 64-float row
    const int half   = lane >> 4;          // 0/1: which of each pair of positions
    const int warp   = threadIdx.x >> 5;

    const int gwarp  = blockIdx.x * WARPS_PB + warp;
    const int nwarps = gridDim.x * WARPS_PB;
    const int stride = nwarps * 32;
    float4* __restrict__ o4 = reinterpret_cast<float4*>(out);

    #pragma unroll 1
    for (int base = gwarp * 32; base < NPOS; base += stride) {
        // x is read once: evict-first so it never displaces the table in L1
        const int xv = __ldcs(&x[base + lane]);        // coalesced 128B

        // warp covers 32 consecutive positions; store addrs = wbase + k*512B
        float4* wbase = o4 + ((size_t)base + half) * (D / 4) + lane15;
        #pragma unroll
        for (int k = 0; k < 16; ++k) {
            const int xi = __shfl_sync(0xffffffffu, xv, 2 * k + half);
            const float4 v = __ldg(&gt4[xi * (D / 4) + lane15]);  // L1 hit
            __stcs(wbase + k * 2 * (D / 4), v);        // streaming store
        }
    }
}

extern "C" void kernel_launch(void* const* d_in, const int* in_sizes, int n_in,
                              void* d_out, int out_size) {
    const int*   x = (const int*)  d_in[0];
    const float* W = (const float*)d_in[1];
    const float* b = (const float*)d_in[2];
    float*     out = (float*)d_out;

    build_kernel<<<1, TPB>>>(W, b);

    // Persistent grid: 152 SMs * 8 CTAs (no smem, <=32 regs)
    const int grid = 152 * 8;
    gather_kernel<<<grid, TPB>>>(x, out);
}

// round 9
// speedup vs baseline: 1.1214x; 1.0426x over previous
#include <cuda_runtime.h>

// out[p, :] = cumsum(W, axis=1)[:, x[p]] + b, p in [0, 8192*200)
// x: int32 (NPOS), W: fp32 (64,129) row-major, b: fp32 (64), out: fp32 (NPOS*64)

#define F1 129                  // num_feature + 1
#define D  64                   // vector dim
#define NPOS (8192 * 200)       // 1,638,400 positions (divisible by 32)
#define TPB 256
#define WARPS_PB (TPB / 32)

// Lookup table in global memory (L1-resident during gather):
// g_table[c*D + d] = b[d] + sum_{j<=c} W[d*F1 + j]
__device__ float g_table[F1 * D];

// ---- parallel build: 64 blocks, 1 warp each; warp-scan of one dim ----
__global__ void build_kernel(const float* __restrict__ W,
                             const float* __restrict__ b) {
    const int d    = blockIdx.x;           // 0..63
    const int lane = threadIdx.x;          // 0..31
    const float* wrow = W + d * F1;

    float carry = __ldg(&b[d]);
    #pragma unroll
    for (int c0 = 0; c0 < 128; c0 += 32) {
        float v = __ldg(&wrow[c0 + lane]);
        // inclusive warp scan (shfl-up)
        #pragma unroll
        for (int off = 1; off < 32; off <<= 1) {
            float n = __shfl_up_sync(0xffffffffu, v, off);
            if (lane >= off) v += n;
        }
        v += carry;
        g_table[(c0 + lane) * D + d] = v;
        carry = __shfl_sync(0xffffffffu, v, 31);
    }
    if (lane == 0)
        g_table[128 * D + d] = carry + __ldg(&wrow[128]);
}

// ---- gather/store: zero smem, 32 regs -> 8 CTAs/SM (64 warps), table via L1 ----
__global__ void __launch_bounds__(TPB, 8)
gather_kernel(const int* __restrict__ x, float* __restrict__ out) {
    const float4* __restrict__ gt4 = reinterpret_cast<const float4*>(g_table);

    const int lane   = threadIdx.x & 31;
    const int lane15 = lane & 15;          // which float4 within the 64-float row
    const int half   = lane >> 4;          // 0/1: which of each pair of positions
    const int warp   = threadIdx.x >> 5;

    const int gwarp  = blockIdx.x * WARPS_PB + warp;
    const int nwarps = gridDim.x * WARPS_PB;
    const int stride = nwarps * 32;
    float4* __restrict__ o4 = reinterpret_cast<float4*>(out);

    #pragma unroll 1
    for (int base = gwarp * 32; base < NPOS; base += stride) {
        // x is read once: evict-first so it never displaces the table in L1
        const int xv = __ldcs(&x[base + lane]);        // coalesced 128B

        // warp covers 32 consecutive positions; store addrs = wbase + k*512B
        float4* wbase = o4 + ((size_t)base + half) * (D / 4) + lane15;
        #pragma unroll
        for (int k = 0; k < 16; ++k) {
            const int xi = __shfl_sync(0xffffffffu, xv, 2 * k + half);
            const float4 v = __ldg(&gt4[xi * (D / 4) + lane15]);  // L1 hit
            __stcs(wbase + k * 2 * (D / 4), v);        // streaming store
        }
    }
}

extern "C" void kernel_launch(void* const* d_in, const int* in_sizes, int n_in,
                              void* d_out, int out_size) {
    const int*   x = (const int*)  d_in[0];
    const float* W = (const float*)d_in[1];
    const float* b = (const float*)d_in[2];
    float*     out = (float*)d_out;

    build_kernel<<<D, 32>>>(W, b);         // 64 blocks, 1 warp each: <1us

    // Persistent grid: 152 SMs * 8 CTAs (no smem, 32 regs)
    const int grid = 152 * 8;
    gather_kernel<<<grid, TPB>>>(x, out);
}